// round 1
// baseline (speedup 1.0000x reference)
#include <cuda_runtime.h>
#include <cuda_bf16.h>
#include <math.h>

// Problem constants
#define BB 4
#define LL 1024
#define MM (BB*LL)        // 4096 tokens
#define DD 1536           // hidden dim (K and N of GEMM1)

// ---------------------------------------------------------------------------
// Scratch: h = gemm1 output, [M, D] fp32 (25 MB) — static device array (no alloc)
// ---------------------------------------------------------------------------
__device__ float g_h[(size_t)MM * DD];

// mask dtype kind: 0 = uint8/bool, 1 = int32, 2 = float32
__device__ int g_mask_kind;

// ---------------------------------------------------------------------------
// Kernel 0: detect dtype of affine_mask from raw bit pattern (first 4 KB)
// ---------------------------------------------------------------------------
__global__ void detect_mask_kernel(const unsigned int* __restrict__ w) {
    __shared__ int s_not01, s_notF, s_anyF;
    if (threadIdx.x == 0) { s_not01 = 0; s_notF = 0; s_anyF = 0; }
    __syncthreads();
    int not01 = 0, notF = 0, anyF = 0;
    for (int i = threadIdx.x; i < 1024; i += 256) {
        unsigned v = w[i];
        if (v != 0u && v != 1u) not01 = 1;
        if (v != 0u && v != 0x3f800000u) notF = 1;
        if (v == 0x3f800000u) anyF = 1;
    }
    if (not01) atomicOr(&s_not01, 1);
    if (notF)  atomicOr(&s_notF, 1);
    if (anyF)  atomicOr(&s_anyF, 1);
    __syncthreads();
    if (threadIdx.x == 0) {
        int kind;
        if (!s_notF && s_anyF) kind = 2;       // float32 0.0/1.0
        else if (!s_not01)     kind = 1;       // int32 0/1
        else                   kind = 0;       // packed bytes (bool/uint8)
        g_mask_kind = kind;
    }
}

// ---------------------------------------------------------------------------
// Kernel 1: C[m,e] = sum_d A[m,d] * W[e,d] + bias[e]
// A: [M, K] row-major (x), W: [N, K] row-major (w1), C = g_h [M, N]
// 128x128x16 tiles, 8x8 per thread, double-buffered shared memory.
// ---------------------------------------------------------------------------
#define GK DD

__global__ __launch_bounds__(256, 1) void gemm1_kernel(
    const float* __restrict__ A,
    const float* __restrict__ W,
    const float* __restrict__ bias)
{
    __shared__ float As[2][16][128];
    __shared__ float Bs[2][16][128];

    const int tid = threadIdx.x;
    const int bm  = blockIdx.y * 128;
    const int bn  = blockIdx.x * 128;
    const int tm  = (tid >> 4) << 3;   // 0..120
    const int tn  = (tid & 15) << 3;   // 0..120

    const int lr = tid >> 2;           // 0..63  (row within tile)
    const int lc = (tid & 3) << 2;     // 0,4,8,12 (k offset)

    const float* Aptr = A + (size_t)(bm + lr) * GK + lc;
    const float* Wptr = W + (size_t)(bn + lr) * GK + lc;

    float acc[8][8];
    #pragma unroll
    for (int i = 0; i < 8; i++)
        #pragma unroll
        for (int j = 0; j < 8; j++) acc[i][j] = 0.f;

    float4 ra0, ra1, rb0, rb1;

#define LOAD_GMEM(kt) do {                                   \
    const float* Ap = Aptr + (kt) * 16;                      \
    const float* Wp = Wptr + (kt) * 16;                      \
    ra0 = *(const float4*)(Ap);                              \
    ra1 = *(const float4*)(Ap + (size_t)64 * GK);            \
    rb0 = *(const float4*)(Wp);                              \
    rb1 = *(const float4*)(Wp + (size_t)64 * GK);            \
} while (0)

#define STORE_SMEM(buf) do {                                 \
    As[buf][lc+0][lr]    = ra0.x; As[buf][lc+1][lr]    = ra0.y; \
    As[buf][lc+2][lr]    = ra0.z; As[buf][lc+3][lr]    = ra0.w; \
    As[buf][lc+0][lr+64] = ra1.x; As[buf][lc+1][lr+64] = ra1.y; \
    As[buf][lc+2][lr+64] = ra1.z; As[buf][lc+3][lr+64] = ra1.w; \
    Bs[buf][lc+0][lr]    = rb0.x; Bs[buf][lc+1][lr]    = rb0.y; \
    Bs[buf][lc+2][lr]    = rb0.z; Bs[buf][lc+3][lr]    = rb0.w; \
    Bs[buf][lc+0][lr+64] = rb1.x; Bs[buf][lc+1][lr+64] = rb1.y; \
    Bs[buf][lc+2][lr+64] = rb1.z; Bs[buf][lc+3][lr+64] = rb1.w; \
} while (0)

#define COMPUTE(buf) do {                                    \
    _Pragma("unroll")                                        \
    for (int k = 0; k < 16; k++) {                           \
        float av[8], bv[8];                                  \
        *(float4*)&av[0] = *(const float4*)&As[buf][k][tm];      \
        *(float4*)&av[4] = *(const float4*)&As[buf][k][tm + 4];  \
        *(float4*)&bv[0] = *(const float4*)&Bs[buf][k][tn];      \
        *(float4*)&bv[4] = *(const float4*)&Bs[buf][k][tn + 4];  \
        _Pragma("unroll")                                    \
        for (int i = 0; i < 8; i++)                          \
            _Pragma("unroll")                                \
            for (int j = 0; j < 8; j++)                      \
                acc[i][j] += av[i] * bv[j];                  \
    }                                                        \
} while (0)

    LOAD_GMEM(0);
    STORE_SMEM(0);
    __syncthreads();

    int buf = 0;
    const int NKT = GK / 16;  // 96
    for (int kt = 1; kt < NKT; ++kt) {
        LOAD_GMEM(kt);
        COMPUTE(buf);
        buf ^= 1;
        STORE_SMEM(buf);
        __syncthreads();
    }
    COMPUTE(buf);

    // Epilogue: add bias, store to g_h
    float4 bv0 = *(const float4*)&bias[bn + tn];
    float4 bv1 = *(const float4*)&bias[bn + tn + 4];
    #pragma unroll
    for (int i = 0; i < 8; i++) {
        float* Crow = g_h + (size_t)(bm + tm + i) * DD + bn + tn;
        float4 c0 = make_float4(acc[i][0] + bv0.x, acc[i][1] + bv0.y,
                                acc[i][2] + bv0.z, acc[i][3] + bv0.w);
        float4 c1 = make_float4(acc[i][4] + bv1.x, acc[i][5] + bv1.y,
                                acc[i][6] + bv1.z, acc[i][7] + bv1.w);
        *(float4*)(Crow)     = c0;
        *(float4*)(Crow + 4) = c1;
    }
#undef LOAD_GMEM
#undef STORE_SMEM
#undef COMPUTE
}

// ---------------------------------------------------------------------------
// Kernel 2: per-token fused GELU + LayerNorm + 9-way projection + geometry
// grid = 4096 blocks, 256 threads
// ---------------------------------------------------------------------------
__global__ __launch_bounds__(256) void head_kernel(
    const float* __restrict__ ln_g,
    const float* __restrict__ ln_b,
    const float* __restrict__ w2,
    const float* __restrict__ b2,
    const float* __restrict__ affine,
    const unsigned char* __restrict__ maskraw,
    float* __restrict__ out)
{
    const int row = blockIdx.x;
    const int tid = threadIdx.x;
    __shared__ float sh[DD];
    __shared__ float rs[8], rq[8];
    __shared__ float sp[9];

    const float* hrow = g_h + (size_t)row * DD;

    float lsum = 0.f, lsq = 0.f;
    #pragma unroll
    for (int i = 0; i < DD / 256; i++) {
        int idx = tid + i * 256;
        float v = hrow[idx];
        float g = 0.5f * v * (1.f + erff(v * 0.7071067811865475f));
        sh[idx] = g;
        lsum += g;
        lsq  += g * g;
    }
    #pragma unroll
    for (int o = 16; o; o >>= 1) {
        lsum += __shfl_xor_sync(0xffffffffu, lsum, o);
        lsq  += __shfl_xor_sync(0xffffffffu, lsq,  o);
    }
    if ((tid & 31) == 0) { rs[tid >> 5] = lsum; rq[tid >> 5] = lsq; }
    __syncthreads();
    float ts = 0.f, tq = 0.f;
    #pragma unroll
    for (int i = 0; i < 8; i++) { ts += rs[i]; tq += rq[i]; }
    const float inv = 1.f / (float)DD;
    float mu   = ts * inv;
    float var  = tq * inv - mu * mu;
    float rstd = rsqrtf(var + 1e-5f);
    #pragma unroll
    for (int i = 0; i < DD / 256; i++) {
        int idx = tid + i * 256;
        sh[idx] = (sh[idx] - mu) * rstd * ln_g[idx] + ln_b[idx];
    }
    __syncthreads();

    // 9 dot products (only p[0:9] of OUT=23 is ever used by the reference)
    const int warp = tid >> 5, lane = tid & 31;
    for (int o = warp; o < 9; o += 8) {
        const float* wr = w2 + (size_t)o * DD;
        float s = 0.f;
        for (int j = lane; j < DD; j += 32) s += sh[j] * wr[j];
        #pragma unroll
        for (int d = 16; d; d >>= 1) s += __shfl_xor_sync(0xffffffffu, s, d);
        if (lane == 0) sp[o] = s + b2[o];
    }
    __syncthreads();

    if (tid == 0) {
        float tr0 = sp[0] * 10.f, tr1 = sp[1] * 10.f, tr2 = sp[2] * 10.f;
        float xv0 = sp[3], xv1 = sp[4], xv2 = sp[5];
        float yv0 = sp[6], yv1 = sp[7], yv2 = sp[8];
        float nx = sqrtf(xv0*xv0 + xv1*xv1 + xv2*xv2) + 1e-5f;
        xv0 /= nx; xv1 /= nx; xv2 /= nx;
        float ny = sqrtf(yv0*yv0 + yv1*yv1 + yv2*yv2) + 1e-5f;
        yv0 /= ny; yv1 /= ny; yv2 /= ny;
        // Gram-Schmidt on (a = -xv, b = yv)
        float ra = rsqrtf(xv0*xv0 + xv1*xv1 + xv2*xv2 + 1e-12f);
        float e0 = -xv0 * ra, e1 = -xv1 * ra, e2 = -xv2 * ra;
        float d  = e0*yv0 + e1*yv1 + e2*yv2;
        float f0 = yv0 - e0*d, f1 = yv1 - e1*d, f2 = yv2 - e2*d;
        float rb = rsqrtf(f0*f0 + f1*f1 + f2*f2 + 1e-12f);
        f0 *= rb; f1 *= rb; f2 *= rb;
        float g0 = e1*f2 - e2*f1;
        float g1 = e2*f0 - e0*f2;
        float g2 = e0*f1 - e1*f0;

        // mask (dtype decided at runtime)
        int kind = g_mask_kind;
        bool m;
        if (kind == 0)      m = maskraw[row] != 0;
        else if (kind == 1) m = ((const int*)maskraw)[row] != 0;
        else                m = ((const float*)maskraw)[row] != 0.f;

        float Ru[3][3];
        float tu0, tu1, tu2;
        if (m) {
            Ru[0][0] = e0; Ru[0][1] = f0; Ru[0][2] = g0;
            Ru[1][0] = e1; Ru[1][1] = f1; Ru[1][2] = g1;
            Ru[2][0] = e2; Ru[2][1] = f2; Ru[2][2] = g2;
            tu0 = tr0; tu1 = tr1; tu2 = tr2;
        } else {
            Ru[0][0] = 1.f; Ru[0][1] = 0.f; Ru[0][2] = 0.f;
            Ru[1][0] = 0.f; Ru[1][1] = 1.f; Ru[1][2] = 0.f;
            Ru[2][0] = 0.f; Ru[2][1] = 0.f; Ru[2][2] = 1.f;
            tu0 = 0.f; tu1 = 0.f; tu2 = 0.f;
        }

        const float* af = affine + (size_t)row * 12;
        float R[3][3], t[3];
        #pragma unroll
        for (int i = 0; i < 3; i++) {
            float r0 = af[i*3+0], r1 = af[i*3+1], r2 = af[i*3+2];
            #pragma unroll
            for (int j = 0; j < 3; j++)
                R[i][j] = r0 * Ru[0][j] + r1 * Ru[1][j] + r2 * Ru[2][j];
            t[i] = r0 * tu0 + r1 * tu1 + r2 * tu2 + af[9 + i];
        }

        float* ao = out + (size_t)row * 12;
        #pragma unroll
        for (int i = 0; i < 3; i++) {
            ao[i*3+0] = R[i][0]; ao[i*3+1] = R[i][1]; ao[i*3+2] = R[i][2];
            ao[9 + i] = t[i];
        }

        // pred_xyz: BB coords (-0.525,1.363,0), (0,0,0), (1.526,0,0)
        float* px = out + (size_t)MM * 12 + (size_t)row * 9;
        #pragma unroll
        for (int i = 0; i < 3; i++) {
            px[0*3 + i] = R[i][0] * (-0.525f) + R[i][1] * 1.363f + t[i];
            px[1*3 + i] = t[i];
            px[2*3 + i] = R[i][0] * 1.526f + t[i];
        }
    }
}

// ---------------------------------------------------------------------------
// Host launcher
// ---------------------------------------------------------------------------
extern "C" void kernel_launch(void* const* d_in, const int* in_sizes, int n_in,
                              void* d_out, int out_size)
{
    const float* x      = (const float*)d_in[0];
    const float* affine = (const float*)d_in[1];
    const void*  mask   = d_in[2];
    const float* w1     = (const float*)d_in[3];
    const float* b1     = (const float*)d_in[4];
    const float* ln_g   = (const float*)d_in[5];
    const float* ln_b   = (const float*)d_in[6];
    const float* w2     = (const float*)d_in[7];
    const float* b2     = (const float*)d_in[8];
    float* out = (float*)d_out;

    detect_mask_kernel<<<1, 256>>>((const unsigned int*)mask);

    dim3 grid(DD / 128, MM / 128);   // (12, 32)
    gemm1_kernel<<<grid, 256>>>(x, w1, b1);

    head_kernel<<<MM, 256>>>(ln_g, ln_b, w2, b2, affine,
                             (const unsigned char*)mask, out);
}

// round 3
// speedup vs baseline: 2.4786x; 2.4786x over previous
#include <cuda_runtime.h>
#include <cuda_bf16.h>
#include <math.h>
#include <stdint.h>

// Problem constants
#define BB 4
#define LL 1024
#define MM (BB*LL)        // 4096 tokens
#define DD 1536           // hidden dim
#define KK3 (3*DD)        // 4608 : [hi | lo | hi] x [whi | whi | wlo]

// ---------------------------------------------------------------------------
// Scratch (static device arrays; no allocations)
// ---------------------------------------------------------------------------
__device__ float g_h[(size_t)MM * DD];                    // gemm1 output (25 MB)
__device__ __nv_bfloat16 g_Aq[(size_t)MM * KK3];          // split x    (37.7 MB)
__device__ __nv_bfloat16 g_Bq[(size_t)DD * KK3];          // split w1   (14.2 MB)
__device__ int g_mask_kind;

// ---------------------------------------------------------------------------
// Kernel 0: detect dtype of affine_mask from raw bit pattern (first 4 KB)
// ---------------------------------------------------------------------------
__global__ void detect_mask_kernel(const unsigned int* __restrict__ w) {
    __shared__ int s_not01, s_notF, s_anyF;
    if (threadIdx.x == 0) { s_not01 = 0; s_notF = 0; s_anyF = 0; }
    __syncthreads();
    int not01 = 0, notF = 0, anyF = 0;
    for (int i = threadIdx.x; i < 1024; i += 256) {
        unsigned v = w[i];
        if (v != 0u && v != 1u) not01 = 1;
        if (v != 0u && v != 0x3f800000u) notF = 1;
        if (v == 0x3f800000u) anyF = 1;
    }
    if (not01) atomicOr(&s_not01, 1);
    if (notF)  atomicOr(&s_notF, 1);
    if (anyF)  atomicOr(&s_anyF, 1);
    __syncthreads();
    if (threadIdx.x == 0) {
        int kind;
        if (!s_notF && s_anyF) kind = 2;
        else if (!s_not01)     kind = 1;
        else                   kind = 0;
        g_mask_kind = kind;
    }
}

// ---------------------------------------------------------------------------
// Split-conversion kernels (vectorized 4-wide):
// A' row layout: [hi | lo | hi],  B' row layout: [whi | whi | wlo]
// => A'.B' = hi*whi + lo*whi + hi*wlo  (lo*wlo dropped, ~2^-18 relative)
// ---------------------------------------------------------------------------
__global__ void convA_kernel(const float* __restrict__ x) {
    int idx4 = blockIdx.x * 256 + threadIdx.x;          // one float4 per thread
    if (idx4 >= MM * DD / 4) return;
    int m = idx4 / (DD / 4), d4 = idx4 - m * (DD / 4);
    float4 v = ((const float4*)x)[idx4];
    __nv_bfloat16 hi[4], lo[4];
    float vv[4] = {v.x, v.y, v.z, v.w};
    #pragma unroll
    for (int i = 0; i < 4; i++) {
        hi[i] = __float2bfloat16(vv[i]);
        lo[i] = __float2bfloat16(vv[i] - __bfloat162float(hi[i]));
    }
    __nv_bfloat16* row = g_Aq + (size_t)m * KK3 + d4 * 4;
    *(uint2*)(row)          = *(uint2*)hi;
    *(uint2*)(row + DD)     = *(uint2*)lo;
    *(uint2*)(row + 2 * DD) = *(uint2*)hi;
}

__global__ void convB_kernel(const float* __restrict__ w1) {
    int idx4 = blockIdx.x * 256 + threadIdx.x;
    if (idx4 >= DD * DD / 4) return;
    int n = idx4 / (DD / 4), d4 = idx4 - n * (DD / 4);
    float4 v = ((const float4*)w1)[idx4];
    __nv_bfloat16 hi[4], lo[4];
    float vv[4] = {v.x, v.y, v.z, v.w};
    #pragma unroll
    for (int i = 0; i < 4; i++) {
        hi[i] = __float2bfloat16(vv[i]);
        lo[i] = __float2bfloat16(vv[i] - __bfloat162float(hi[i]));
    }
    __nv_bfloat16* row = g_Bq + (size_t)n * KK3 + d4 * 4;
    *(uint2*)(row)          = *(uint2*)hi;
    *(uint2*)(row + DD)     = *(uint2*)hi;
    *(uint2*)(row + 2 * DD) = *(uint2*)lo;
}

// ---------------------------------------------------------------------------
// Kernel 1: tensor-core GEMM  h[m,n] = sum_k A'[m,k] B'[n,k] + b1[n]
// 128x128 block tile, BK=32, 8 warps (each 64x32), mma.sync m16n8k16 bf16
// 2-stage cp.async double buffer.
// ---------------------------------------------------------------------------
#define BKP 40   // padded row length in bf16 elems (80 bytes): conflict-free ldmatrix

__device__ __forceinline__ uint32_t smem_u32(const void* p) {
    return (uint32_t)__cvta_generic_to_shared(p);
}

__global__ __launch_bounds__(256, 1) void gemm1_mma_kernel(
    const float* __restrict__ bias)
{
    __shared__ __nv_bfloat16 As[2][128][BKP];
    __shared__ __nv_bfloat16 Bs[2][128][BKP];

    const int tid  = threadIdx.x;
    const int bm   = blockIdx.y * 128;
    const int bn   = blockIdx.x * 128;
    const int warp = tid >> 5, lane = tid & 31;
    const int wm   = (warp >> 2) * 64;   // 0 or 64
    const int wn   = (warp & 3) * 32;    // 0,32,64,96

    // cp.async loader mapping: 64 rows x 32 cols per 16B op, 2 ops per matrix
    const int ldr = tid >> 2;          // 0..63
    const int ldc = (tid & 3) * 8;     // 0,8,16,24
    const __nv_bfloat16* gA0 = g_Aq + (size_t)(bm + ldr) * KK3 + ldc;
    const __nv_bfloat16* gA1 = gA0 + (size_t)64 * KK3;
    const __nv_bfloat16* gB0 = g_Bq + (size_t)(bn + ldr) * KK3 + ldc;
    const __nv_bfloat16* gB1 = gB0 + (size_t)64 * KK3;

    float acc[4][4][4];
    #pragma unroll
    for (int i = 0; i < 4; i++)
        #pragma unroll
        for (int j = 0; j < 4; j++)
            #pragma unroll
            for (int r = 0; r < 4; r++) acc[i][j][r] = 0.f;

    const int t8 = lane >> 3, r8 = lane & 7;

#define LOAD_STAGE(s, kt) do {                                                \
    int k0 = (kt) * 32;                                                       \
    uint32_t dA0 = smem_u32(&As[s][ldr][ldc]);                                \
    uint32_t dA1 = smem_u32(&As[s][ldr + 64][ldc]);                           \
    uint32_t dB0 = smem_u32(&Bs[s][ldr][ldc]);                                \
    uint32_t dB1 = smem_u32(&Bs[s][ldr + 64][ldc]);                           \
    asm volatile("cp.async.cg.shared.global [%0], [%1], 16;\n" ::             \
                 "r"(dA0), "l"(gA0 + k0));                                    \
    asm volatile("cp.async.cg.shared.global [%0], [%1], 16;\n" ::             \
                 "r"(dA1), "l"(gA1 + k0));                                    \
    asm volatile("cp.async.cg.shared.global [%0], [%1], 16;\n" ::             \
                 "r"(dB0), "l"(gB0 + k0));                                    \
    asm volatile("cp.async.cg.shared.global [%0], [%1], 16;\n" ::             \
                 "r"(dB1), "l"(gB1 + k0));                                    \
    asm volatile("cp.async.commit_group;\n");                                 \
} while (0)

#define COMPUTE_STAGE(s) do {                                                 \
    _Pragma("unroll")                                                         \
    for (int k16 = 0; k16 < 32; k16 += 16) {                                  \
        uint32_t a[4][4], b[2][4];                                            \
        _Pragma("unroll")                                                     \
        for (int mf = 0; mf < 4; mf++) {                                      \
            uint32_t addr = smem_u32(                                         \
                &As[s][wm + mf * 16 + (t8 & 1) * 8 + r8]                      \
                     [k16 + (t8 >> 1) * 8]);                                  \
            asm volatile(                                                     \
                "ldmatrix.sync.aligned.m8n8.x4.shared.b16 "                   \
                "{%0,%1,%2,%3}, [%4];\n"                                      \
                : "=r"(a[mf][0]), "=r"(a[mf][1]),                             \
                  "=r"(a[mf][2]), "=r"(a[mf][3]) : "r"(addr));                \
        }                                                                     \
        _Pragma("unroll")                                                     \
        for (int np = 0; np < 2; np++) {                                      \
            uint32_t addr = smem_u32(                                         \
                &Bs[s][wn + np * 16 + (t8 >> 1) * 8 + r8]                     \
                     [k16 + (t8 & 1) * 8]);                                   \
            asm volatile(                                                     \
                "ldmatrix.sync.aligned.m8n8.x4.shared.b16 "                   \
                "{%0,%1,%2,%3}, [%4];\n"                                      \
                : "=r"(b[np][0]), "=r"(b[np][1]),                             \
                  "=r"(b[np][2]), "=r"(b[np][3]) : "r"(addr));                \
        }                                                                     \
        _Pragma("unroll")                                                     \
        for (int mf = 0; mf < 4; mf++) {                                      \
            _Pragma("unroll")                                                 \
            for (int nf = 0; nf < 4; nf++) {                                  \
                uint32_t b0 = b[nf >> 1][(nf & 1) * 2];                       \
                uint32_t b1 = b[nf >> 1][(nf & 1) * 2 + 1];                   \
                asm volatile(                                                 \
                    "mma.sync.aligned.m16n8k16.row.col.f32.bf16.bf16.f32 "    \
                    "{%0,%1,%2,%3}, {%4,%5,%6,%7}, {%8,%9}, {%0,%1,%2,%3};\n" \
                    : "+f"(acc[mf][nf][0]), "+f"(acc[mf][nf][1]),             \
                      "+f"(acc[mf][nf][2]), "+f"(acc[mf][nf][3])              \
                    : "r"(a[mf][0]), "r"(a[mf][1]),                           \
                      "r"(a[mf][2]), "r"(a[mf][3]), "r"(b0), "r"(b1));        \
            }                                                                 \
        }                                                                     \
    }                                                                         \
} while (0)

    const int NKT = KK3 / 32;   // 144
    LOAD_STAGE(0, 0);
    for (int kt = 0; kt < NKT; ++kt) {
        asm volatile("cp.async.wait_group 0;\n");
        __syncthreads();
        if (kt + 1 < NKT) LOAD_STAGE((kt + 1) & 1, kt + 1);
        COMPUTE_STAGE(kt & 1);
        __syncthreads();
    }

    // Epilogue: bias + store fp32 h
    const int cr = lane >> 2;          // 0..7
    const int cc = (lane & 3) * 2;     // 0,2,4,6
    #pragma unroll
    for (int mf = 0; mf < 4; mf++) {
        #pragma unroll
        for (int nf = 0; nf < 4; nf++) {
            int row = bm + wm + mf * 16 + cr;
            int col = bn + wn + nf * 8 + cc;
            float bv0 = bias[col], bv1 = bias[col + 1];
            float* p0 = g_h + (size_t)row * DD + col;
            float* p1 = g_h + (size_t)(row + 8) * DD + col;
            p0[0] = acc[mf][nf][0] + bv0;
            p0[1] = acc[mf][nf][1] + bv1;
            p1[0] = acc[mf][nf][2] + bv0;
            p1[1] = acc[mf][nf][3] + bv1;
        }
    }
#undef LOAD_STAGE
#undef COMPUTE_STAGE
}

// ---------------------------------------------------------------------------
// Kernel 2: per-token fused GELU + LayerNorm + 9-way projection + geometry
// ---------------------------------------------------------------------------
__global__ __launch_bounds__(256) void head_kernel(
    const float* __restrict__ ln_g,
    const float* __restrict__ ln_b,
    const float* __restrict__ w2,
    const float* __restrict__ b2,
    const float* __restrict__ affine,
    const unsigned char* __restrict__ maskraw,
    float* __restrict__ out)
{
    const int row = blockIdx.x;
    const int tid = threadIdx.x;
    __shared__ float sh[DD];
    __shared__ float rs[8], rq[8];
    __shared__ float sp[9];

    const float* hrow = g_h + (size_t)row * DD;

    float lsum = 0.f, lsq = 0.f;
    #pragma unroll
    for (int i = 0; i < DD / 256; i++) {
        int idx = tid + i * 256;
        float v = hrow[idx];
        float g = 0.5f * v * (1.f + erff(v * 0.7071067811865475f));
        sh[idx] = g;
        lsum += g;
        lsq  += g * g;
    }
    #pragma unroll
    for (int o = 16; o; o >>= 1) {
        lsum += __shfl_xor_sync(0xffffffffu, lsum, o);
        lsq  += __shfl_xor_sync(0xffffffffu, lsq,  o);
    }
    if ((tid & 31) == 0) { rs[tid >> 5] = lsum; rq[tid >> 5] = lsq; }
    __syncthreads();
    float ts = 0.f, tq = 0.f;
    #pragma unroll
    for (int i = 0; i < 8; i++) { ts += rs[i]; tq += rq[i]; }
    const float inv = 1.f / (float)DD;
    float mu   = ts * inv;
    float var  = tq * inv - mu * mu;
    float rstd = rsqrtf(var + 1e-5f);
    #pragma unroll
    for (int i = 0; i < DD / 256; i++) {
        int idx = tid + i * 256;
        sh[idx] = (sh[idx] - mu) * rstd * ln_g[idx] + ln_b[idx];
    }
    __syncthreads();

    const int warp = tid >> 5, lane = tid & 31;
    for (int o = warp; o < 9; o += 8) {
        const float* wr = w2 + (size_t)o * DD;
        float s = 0.f;
        for (int j = lane; j < DD; j += 32) s += sh[j] * wr[j];
        #pragma unroll
        for (int d = 16; d; d >>= 1) s += __shfl_xor_sync(0xffffffffu, s, d);
        if (lane == 0) sp[o] = s + b2[o];
    }
    __syncthreads();

    if (tid == 0) {
        float tr0 = sp[0] * 10.f, tr1 = sp[1] * 10.f, tr2 = sp[2] * 10.f;
        float xv0 = sp[3], xv1 = sp[4], xv2 = sp[5];
        float yv0 = sp[6], yv1 = sp[7], yv2 = sp[8];
        float nx = sqrtf(xv0*xv0 + xv1*xv1 + xv2*xv2) + 1e-5f;
        xv0 /= nx; xv1 /= nx; xv2 /= nx;
        float ny = sqrtf(yv0*yv0 + yv1*yv1 + yv2*yv2) + 1e-5f;
        yv0 /= ny; yv1 /= ny; yv2 /= ny;
        float ra = rsqrtf(xv0*xv0 + xv1*xv1 + xv2*xv2 + 1e-12f);
        float e0 = -xv0 * ra, e1 = -xv1 * ra, e2 = -xv2 * ra;
        float d  = e0*yv0 + e1*yv1 + e2*yv2;
        float f0 = yv0 - e0*d, f1 = yv1 - e1*d, f2 = yv2 - e2*d;
        float rb = rsqrtf(f0*f0 + f1*f1 + f2*f2 + 1e-12f);
        f0 *= rb; f1 *= rb; f2 *= rb;
        float g0 = e1*f2 - e2*f1;
        float g1 = e2*f0 - e0*f2;
        float g2 = e0*f1 - e1*f0;

        int kind = g_mask_kind;
        bool m;
        if (kind == 0)      m = maskraw[row] != 0;
        else if (kind == 1) m = ((const int*)maskraw)[row] != 0;
        else                m = ((const float*)maskraw)[row] != 0.f;

        float Ru[3][3];
        float tu0, tu1, tu2;
        if (m) {
            Ru[0][0] = e0; Ru[0][1] = f0; Ru[0][2] = g0;
            Ru[1][0] = e1; Ru[1][1] = f1; Ru[1][2] = g1;
            Ru[2][0] = e2; Ru[2][1] = f2; Ru[2][2] = g2;
            tu0 = tr0; tu1 = tr1; tu2 = tr2;
        } else {
            Ru[0][0] = 1.f; Ru[0][1] = 0.f; Ru[0][2] = 0.f;
            Ru[1][0] = 0.f; Ru[1][1] = 1.f; Ru[1][2] = 0.f;
            Ru[2][0] = 0.f; Ru[2][1] = 0.f; Ru[2][2] = 1.f;
            tu0 = 0.f; tu1 = 0.f; tu2 = 0.f;
        }

        const float* af = affine + (size_t)row * 12;
        float R[3][3], t[3];
        #pragma unroll
        for (int i = 0; i < 3; i++) {
            float r0 = af[i*3+0], r1 = af[i*3+1], r2 = af[i*3+2];
            #pragma unroll
            for (int j = 0; j < 3; j++)
                R[i][j] = r0 * Ru[0][j] + r1 * Ru[1][j] + r2 * Ru[2][j];
            t[i] = r0 * tu0 + r1 * tu1 + r2 * tu2 + af[9 + i];
        }

        float* ao = out + (size_t)row * 12;
        #pragma unroll
        for (int i = 0; i < 3; i++) {
            ao[i*3+0] = R[i][0]; ao[i*3+1] = R[i][1]; ao[i*3+2] = R[i][2];
            ao[9 + i] = t[i];
        }

        float* px = out + (size_t)MM * 12 + (size_t)row * 9;
        #pragma unroll
        for (int i = 0; i < 3; i++) {
            px[0*3 + i] = R[i][0] * (-0.525f) + R[i][1] * 1.363f + t[i];
            px[1*3 + i] = t[i];
            px[2*3 + i] = R[i][0] * 1.526f + t[i];
        }
    }
}

// ---------------------------------------------------------------------------
// Host launcher
// ---------------------------------------------------------------------------
extern "C" void kernel_launch(void* const* d_in, const int* in_sizes, int n_in,
                              void* d_out, int out_size)
{
    const float* x      = (const float*)d_in[0];
    const float* affine = (const float*)d_in[1];
    const void*  mask   = d_in[2];
    const float* w1     = (const float*)d_in[3];
    const float* b1     = (const float*)d_in[4];
    const float* ln_g   = (const float*)d_in[5];
    const float* ln_b   = (const float*)d_in[6];
    const float* w2     = (const float*)d_in[7];
    const float* b2     = (const float*)d_in[8];
    float* out = (float*)d_out;

    detect_mask_kernel<<<1, 256>>>((const unsigned int*)mask);

    convA_kernel<<<(MM * DD / 4 + 255) / 256, 256>>>(x);
    convB_kernel<<<(DD * DD / 4 + 255) / 256, 256>>>(w1);

    dim3 grid(DD / 128, MM / 128);   // (12, 32)
    gemm1_mma_kernel<<<grid, 256>>>(b1);

    head_kernel<<<MM, 256>>>(ln_g, ln_b, w2, b2, affine,
                             (const unsigned char*)mask, out);
}